// round 2
// baseline (speedup 1.0000x reference)
#include <cuda_runtime.h>
#include <cstdint>

#define BB      16
#define CC      30
#define TOPK    200
#define MAXDET  100
#define CAP     4096          // global per-(b,c) candidate capacity
#define CAPSH   2048          // shared sort capacity in k_nms
#define POOLCAP 3072          // per-image merge pool capacity (<= 30*100)
#define NBIN    256
#define SAMP    16
#define SUFF_TARGET 48

typedef unsigned long long u64;
typedef unsigned int u32;

// ---------------- scratch (device globals; no allocations) ----------------
__device__ int d_hist[BB * CC * NBIN];
__device__ int d_binlo[BB * CC];
__device__ int d_candcnt[BB * CC];
__device__ u64 d_cand[(size_t)BB * CC * CAP];
__device__ int d_nms_i[BB * CC * TOPK];         // anchor index per (b,c,slot)
__device__ u64 d_pool[BB * POOLCAP];            // per-image merge keys
__device__ int d_poolcnt[BB];

// ---------------- helpers ----------------
__device__ __forceinline__ void bitonic_sort_desc(u64* s, int n, int tid, int nt) {
    for (int k = 2; k <= n; k <<= 1) {
        for (int j = k >> 1; j > 0; j >>= 1) {
            for (int t = tid; t < n; t += nt) {
                int ixj = t ^ j;
                if (ixj > t) {
                    u64 a = s[t], b = s[ixj];
                    bool up = (t & k) == 0;
                    bool sw = up ? (a < b) : (a > b);
                    if (sw) { s[t] = b; s[ixj] = a; }
                }
            }
            __syncthreads();
        }
    }
}

// ---------------- kernels ----------------
__global__ void k_zero() {
    int t = blockIdx.x * blockDim.x + threadIdx.x;
    int stride = gridDim.x * blockDim.x;
    for (int i = t; i < BB * CC * NBIN; i += stride) d_hist[i] = 0;
    for (int i = t; i < BB * CC; i += stride) d_candcnt[i] = 0;
    for (int i = t; i < BB; i += stride) d_poolcnt[i] = 0;
}

// Sampled histogram over the FIRST N/SAMP rows (contiguous, coalesced).
__global__ __launch_bounds__(512) void k_hist(const float* __restrict__ cls, int N) {
    __shared__ int h[CC * NBIN];
    int b = blockIdx.y, tid = threadIdx.x;
    for (int t = tid; t < CC * NBIN; t += 512) h[t] = 0;
    __syncthreads();

    int nS = N / SAMP;                         // 6250 rows
    int tot4 = (nS * CC) / 4;                  // float4 count (187500/4 = 46875)
    int per = (tot4 + gridDim.x - 1) / gridDim.x;
    int v0 = blockIdx.x * per;
    int v1 = min(tot4, v0 + per);
    const float4* p4 = reinterpret_cast<const float4*>(cls + (size_t)b * N * CC);

    for (int v = v0 + tid; v < v1; v += 512) {
        float4 q = p4[v];
        int e = v << 2;
        float vals[4] = {q.x, q.y, q.z, q.w};
        #pragma unroll
        for (int j = 0; j < 4; j++) {
            float x = vals[j];
            if (x > 0.01f) {
                int bin = (int)(x * 256.0f); bin = bin > 255 ? 255 : bin;
                int c = (u32)(e + j) % CC;
                atomicAdd(&h[c * NBIN + bin], 1);
            }
        }
    }
    __syncthreads();
    for (int t = tid; t < CC * NBIN; t += 512) {
        int v = h[t];
        if (v) atomicAdd(&d_hist[b * CC * NBIN + t], v);
    }
}

__global__ void k_thresh() {
    int pc = blockIdx.x * blockDim.x + threadIdx.x;
    if (pc >= BB * CC) return;
    int acc = 0, lo = 0;
    for (int s = NBIN - 1; s >= 0; s--) {
        acc += d_hist[pc * NBIN + s];
        if (acc >= SUFF_TARGET) { lo = s; break; }
    }
    d_binlo[pc] = lo;
}

// Full pass: collect candidates. High-MLP unrolled float4 loads, int32 math.
__device__ __forceinline__ void coll_elem(float val, int ee, int b,
                                          const float* __restrict__ sthr) {
    if (val > 0.01f) {
        u32 c = (u32)ee % CC;
        if (val >= sthr[c]) {
            int i = (u32)ee / CC;
            int pcc = b * CC + (int)c;
            int p = atomicAdd(&d_candcnt[pcc], 1);
            if (p < CAP)
                d_cand[(size_t)pcc * CAP + p] =
                    ((u64)__float_as_uint(val) << 32) | (u64)(u32)(~(u32)i);
        }
    }
}

__device__ __forceinline__ void coll_quad(float4 q, int e, int b, float fgate,
                                          const float* __restrict__ sthr) {
    float m = fmaxf(fmaxf(q.x, q.y), fmaxf(q.z, q.w));
    if (m >= fgate) {
        coll_elem(q.x, e + 0, b, sthr);
        coll_elem(q.y, e + 1, b, sthr);
        coll_elem(q.z, e + 2, b, sthr);
        coll_elem(q.w, e + 3, b, sthr);
    }
}

__global__ __launch_bounds__(512) void k_collect(const float* __restrict__ cls, int N) {
    __shared__ float sthr[CC];
    __shared__ float sgate;
    int b = blockIdx.y, tid = threadIdx.x;
    if (tid < CC) sthr[tid] = (float)d_binlo[b * CC + tid] * 0.00390625f;
    __syncthreads();
    if (tid == 0) {
        float mn = 1e9f;
        for (int c = 0; c < CC; c++) mn = fminf(mn, sthr[c]);
        sgate = fmaxf(0.01f, mn);
    }
    __syncthreads();
    float fgate = sgate;

    int tot4 = (N * CC) / 4;                       // 750000
    int per = tot4 / gridDim.x;                    // gridDim.x divides tot4
    int v0 = blockIdx.x * per;
    const float4* p4 = reinterpret_cast<const float4*>(cls + (size_t)b * N * CC);

    int v = v0 + tid;
    int vend = v0 + per;
    for (; v + 3 * 512 < vend; v += 4 * 512) {
        float4 q0 = p4[v];
        float4 q1 = p4[v + 512];
        float4 q2 = p4[v + 1024];
        float4 q3 = p4[v + 1536];
        coll_quad(q0, v << 2, b, fgate, sthr);
        coll_quad(q1, (v + 512) << 2, b, fgate, sthr);
        coll_quad(q2, (v + 1024) << 2, b, fgate, sthr);
        coll_quad(q3, (v + 1536) << 2, b, fgate, sthr);
    }
    for (; v < vend; v += 512) {
        float4 q = p4[v];
        coll_quad(q, v << 2, b, fgate, sthr);
    }
}

// Per (b,c): exact top-200 + greedy NMS; emit compacted merge keys to pool.
__global__ __launch_bounds__(512) void k_nms(const float* __restrict__ cls,
                                             const float* __restrict__ boxes, int N) {
    __shared__ u64 keys[CAPSH];
    __shared__ float sx1[TOPK], sy1[TOPK], sx2[TOPK], sy2[TOPK], sar[TOPK];
    __shared__ u64 smask[TOPK * 4];
    __shared__ u64 skeep[4];
    __shared__ u32 kw32[8];
    __shared__ int fh[NBIN];
    __shared__ int s_flo, s_fc;

    int pc = blockIdx.x;
    int b = pc / CC, c = pc % CC;
    int tid = threadIdx.x;

    int cnt = d_candcnt[pc];
    int lo = d_binlo[pc];
    bool good = (cnt <= CAPSH) && (cnt >= TOPK || lo == 0);

    int n;
    if (good) {
        int m = min(cnt, CAPSH);
        n = 256;
        while (n < m) n <<= 1;
        for (int t = tid; t < n; t += 512)
            keys[t] = (t < m) ? d_cand[(size_t)pc * CAP + t] : 0ull;
    } else {
        // exact fallback: full strided scan for this (b,c)
        n = CAPSH;
        if (tid < NBIN) fh[tid] = 0;
        if (tid == 0) s_fc = 0;
        __syncthreads();
        const float* col = cls + ((size_t)b * N) * CC + c;
        for (int i = tid; i < N; i += 512) {
            float v = col[(size_t)i * CC];
            if (v > 0.01f) {
                int bin = (int)(v * 256.0f); bin = bin > 255 ? 255 : bin;
                atomicAdd(&fh[bin], 1);
            }
        }
        __syncthreads();
        if (tid == 0) {
            int acc = 0, l2 = 0;
            for (int s = NBIN - 1; s >= 0; s--) {
                acc += fh[s];
                if (acc >= TOPK) { l2 = s; break; }
            }
            s_flo = l2;
        }
        for (int t = tid; t < CAPSH; t += 512) keys[t] = 0ull;
        __syncthreads();
        float lof = (float)s_flo * 0.00390625f;
        for (int i = tid; i < N; i += 512) {
            float v = col[(size_t)i * CC];
            if (v > 0.01f && v >= lof) {
                int p = atomicAdd(&s_fc, 1);
                if (p < CAPSH)
                    keys[p] = ((u64)__float_as_uint(v) << 32) | (u64)(u32)(~(u32)i);
            }
        }
    }
    __syncthreads();
    bitonic_sort_desc(keys, n, tid, 512);

    if (tid < TOPK) {
        u64 k = keys[tid];
        if (k) {
            int id = (int)~(u32)(k & 0xFFFFFFFFull);
            float4 bx = reinterpret_cast<const float4*>(boxes)[(size_t)b * N + id];
            sx1[tid] = bx.x; sy1[tid] = bx.y; sx2[tid] = bx.z; sy2[tid] = bx.w;
            sar[tid] = fmaxf(bx.z - bx.x, 0.0f) * fmaxf(bx.w - bx.y, 0.0f);
        } else {
            sx1[tid] = 1e30f; sy1[tid] = 1e30f; sx2[tid] = -1e30f; sy2[tid] = -1e30f;
            sar[tid] = 0.0f;
        }
    }
    __syncthreads();

    if (tid < TOPK) {
        u64 m0 = 0, m1 = 0, m2 = 0, m3 = 0;
        float x1 = sx1[tid], y1 = sy1[tid], x2 = sx2[tid], y2 = sy2[tid], a = sar[tid];
        for (int j = tid + 1; j < TOPK; j++) {
            float xx1 = fmaxf(x1, sx1[j]), yy1 = fmaxf(y1, sy1[j]);
            float xx2 = fminf(x2, sx2[j]), yy2 = fminf(y2, sy2[j]);
            float inter = fmaxf(xx2 - xx1, 0.0f) * fmaxf(yy2 - yy1, 0.0f);
            float uni = a + sar[j] - inter;
            float iou = inter / fmaxf(uni, 1e-8f);
            if (iou > 0.5f) {
                if (j < 64)       m0 |= 1ull << j;
                else if (j < 128) m1 |= 1ull << (j - 64);
                else if (j < 192) m2 |= 1ull << (j - 128);
                else              m3 |= 1ull << (j - 192);
            }
        }
        smask[tid * 4 + 0] = m0; smask[tid * 4 + 1] = m1;
        smask[tid * 4 + 2] = m2; smask[tid * 4 + 3] = m3;
    }

    // valid words via ballot
    {
        unsigned pred = (tid < TOPK) && (keys[tid] != 0ull);
        unsigned bal = __ballot_sync(0xFFFFFFFFu, pred);
        int w = tid >> 5;
        if ((tid & 31) == 0 && w < 8) kw32[w] = bal;
    }
    __syncthreads();

    // greedy sweep (matches reference fori_loop)
    if (tid == 0) {
        u64 kw[4];
        #pragma unroll
        for (int w = 0; w < 4; w++)
            kw[w] = (u64)kw32[2 * w] | ((u64)kw32[2 * w + 1] << 32);
        for (int i = 0; i < TOPK; i++) {
            if ((kw[i >> 6] >> (i & 63)) & 1ull) {
                kw[0] &= ~smask[i * 4 + 0];
                kw[1] &= ~smask[i * 4 + 1];
                kw[2] &= ~smask[i * 4 + 2];
                kw[3] &= ~smask[i * 4 + 3];
            }
        }
        skeep[0] = kw[0]; skeep[1] = kw[1]; skeep[2] = kw[2]; skeep[3] = kw[3];
    }
    __syncthreads();

    if (tid < TOPK) {
        u64 k = keys[tid];
        d_nms_i[pc * TOPK + tid] = k ? (int)~(u32)(k & 0xFFFFFFFFull) : 0;
        bool kept = (k != 0ull) && (((skeep[tid >> 6] >> (tid & 63)) & 1ull) != 0ull);
        if (kept) {
            // within-class kept rank; only top-100 kept can matter for image top-100
            int w = tid >> 6, bit = tid & 63;
            int rank = 0;
            for (int x = 0; x < w; x++) rank += __popcll(skeep[x]);
            rank += __popcll(skeep[w] & ((bit == 0) ? 0ull : ((1ull << bit) - 1ull)));
            if (rank < MAXDET) {
                int pos = c * TOPK + tid;
                u64 key = ((k >> 32) << 13) | (u64)(8191 - pos);
                int p = atomicAdd(&d_poolcnt[b], 1);
                if (p < POOLCAP) d_pool[b * POOLCAP + p] = key;
            }
        }
    }
}

// Per-image merge: sort pool (<=3000 keys), write top-100 detections.
__global__ __launch_bounds__(1024) void k_merge(const float* __restrict__ boxes,
                                                const float* __restrict__ rot,
                                                const float* __restrict__ tr,
                                                float* __restrict__ out, int N) {
    __shared__ u64 skeys[4096];
    int b = blockIdx.x, tid = threadIdx.x;
    int cnt = min(d_poolcnt[b], POOLCAP);
    int n = 128;
    while (n < cnt) n <<= 1;    // <= 4096
    for (int t = tid; t < n; t += 1024)
        skeys[t] = (t < cnt) ? d_pool[b * POOLCAP + t] : 0ull;
    __syncthreads();
    bitonic_sort_desc(skeys, n, tid, 1024);

    const int SC_OFF = BB * MAXDET * 4;   // 6400
    const int LB_OFF = BB * MAXDET * 5;   // 8000
    const int RT_OFF = BB * MAXDET * 6;   // 9600
    const int TR_OFF = BB * MAXDET * 9;   // 14400

    if (tid < MAXDET) {
        int o = b * MAXDET + tid;
        u64 k = skeys[tid];
        if (k) {
            float s = __uint_as_float((u32)(k >> 13));
            int pos = 8191 - (int)(k & 8191ull);
            int c = pos / TOPK;
            int idx = d_nms_i[b * CC * TOPK + pos];
            float4 bx = reinterpret_cast<const float4*>(boxes)[(size_t)b * N + idx];
            out[o * 4 + 0] = bx.x; out[o * 4 + 1] = bx.y;
            out[o * 4 + 2] = bx.z; out[o * 4 + 3] = bx.w;
            out[SC_OFF + o] = s;
            out[LB_OFF + o] = (float)c;
            size_t rb = ((size_t)b * N + idx) * 3;
            out[RT_OFF + o * 3 + 0] = rot[rb + 0];
            out[RT_OFF + o * 3 + 1] = rot[rb + 1];
            out[RT_OFF + o * 3 + 2] = rot[rb + 2];
            out[TR_OFF + o * 3 + 0] = tr[rb + 0];
            out[TR_OFF + o * 3 + 1] = tr[rb + 1];
            out[TR_OFF + o * 3 + 2] = tr[rb + 2];
        } else {
            out[o * 4 + 0] = -1.0f; out[o * 4 + 1] = -1.0f;
            out[o * 4 + 2] = -1.0f; out[o * 4 + 3] = -1.0f;
            out[SC_OFF + o] = -1.0f;
            out[LB_OFF + o] = -1.0f;
            out[RT_OFF + o * 3 + 0] = -1.0f;
            out[RT_OFF + o * 3 + 1] = -1.0f;
            out[RT_OFF + o * 3 + 2] = -1.0f;
            out[TR_OFF + o * 3 + 0] = -1.0f;
            out[TR_OFF + o * 3 + 1] = -1.0f;
            out[TR_OFF + o * 3 + 2] = -1.0f;
        }
    }
}

// ---------------- launch ----------------
extern "C" void kernel_launch(void* const* d_in, const int* in_sizes, int n_in,
                              void* d_out, int out_size) {
    const float* boxes = (const float*)d_in[0];
    const float* cls   = (const float*)d_in[1];
    const float* rot   = (const float*)d_in[2];
    const float* tr    = (const float*)d_in[3];
    float* out = (float*)d_out;
    int N = in_sizes[0] / (BB * 4);

    k_zero<<<96, 256>>>();
    k_hist<<<dim3(8, BB), 512>>>(cls, N);
    k_thresh<<<2, 256>>>();
    k_collect<<<dim3(125, BB), 512>>>(cls, N);   // 125 divides 750000 float4s
    k_nms<<<BB * CC, 512>>>(cls, boxes, N);
    k_merge<<<BB, 1024>>>(boxes, rot, tr, out, N);
}

// round 4
// speedup vs baseline: 1.4150x; 1.4150x over previous
#include <cuda_runtime.h>
#include <cstdint>

#define BB      16
#define CC      30
#define TOPK    200
#define MAXDET  100
#define CAPSH   2048          // per-(b,c) candidate capacity (shared sort size cap)
#define POOLCAP 3072
#define THRESH  0.995f

typedef unsigned long long u64;
typedef unsigned int u32;

// ---------------- scratch (device globals; no allocations) ----------------
__device__ int d_candcnt[BB * CC];
__device__ u64 d_cand[(size_t)BB * CC * CAPSH];
__device__ int d_nms_i[BB * CC * TOPK];
__device__ u64 d_pool[BB * POOLCAP];
__device__ int d_poolcnt[BB];

// ---------------- helpers ----------------
__device__ __forceinline__ void bitonic_sort_desc(u64* s, int n, int tid, int nt) {
    for (int k = 2; k <= n; k <<= 1) {
        for (int j = k >> 1; j > 0; j >>= 1) {
            for (int t = tid; t < n; t += nt) {
                int ixj = t ^ j;
                if (ixj > t) {
                    u64 a = s[t], b = s[ixj];
                    bool up = (t & k) == 0;
                    bool sw = up ? (a < b) : (a > b);
                    if (sw) { s[t] = b; s[ixj] = a; }
                }
            }
            __syncthreads();
        }
    }
}

// ---------------- kernels ----------------
__global__ void k_zero() {
    int t = threadIdx.x;
    if (t < BB * CC) d_candcnt[t] = 0;
    if (t < BB) d_poolcnt[t] = 0;
}

// One full contiguous pass. Front-batched 8x float4 loads -> single gate compare.
__device__ __forceinline__ void coll_elem(float val, int ee, int N) {
    if (val >= THRESH) {
        u32 c = (u32)ee % CC;
        u32 r = (u32)ee / CC;           // flat row over all images
        u32 b = r / (u32)N;
        u32 i = r - b * (u32)N;
        int pcc = (int)(b * CC + c);
        int p = atomicAdd(&d_candcnt[pcc], 1);
        if (p < CAPSH)
            d_cand[(size_t)pcc * CAPSH + p] =
                ((u64)__float_as_uint(val) << 32) | (u64)(u32)(~i);
    }
}

__global__ __launch_bounds__(512) void k_collect(const float* __restrict__ cls,
                                                 int tot4, int N) {
    const float4* p4 = reinterpret_cast<const float4*>(cls);
    const float4 z4 = make_float4(0.f, 0.f, 0.f, 0.f);
    int ntiles = (tot4 + 4096 - 1) / 4096;           // tile = 512 threads * 8 quads
    for (int tile = blockIdx.x; tile < ntiles; tile += gridDim.x) {
        int v0 = tile * 4096 + threadIdx.x;
        float4 q[8];
        #pragma unroll
        for (int j = 0; j < 8; j++) {
            int idx = v0 + j * 512;
            q[j] = (idx < tot4) ? p4[idx] : z4;
        }
        float m = -1.f;
        #pragma unroll
        for (int j = 0; j < 8; j++)
            m = fmaxf(m, fmaxf(fmaxf(q[j].x, q[j].y), fmaxf(q[j].z, q[j].w)));
        if (m >= THRESH) {
            #pragma unroll
            for (int j = 0; j < 8; j++) {
                float mq = fmaxf(fmaxf(q[j].x, q[j].y), fmaxf(q[j].z, q[j].w));
                if (mq >= THRESH) {
                    int e = (v0 + j * 512) << 2;
                    coll_elem(q[j].x, e + 0, N);
                    coll_elem(q[j].y, e + 1, N);
                    coll_elem(q[j].z, e + 2, N);
                    coll_elem(q[j].w, e + 3, N);
                }
            }
        }
    }
}

// Per (b,c): exact top-200 + greedy NMS; emit compacted merge keys to pool.
__global__ __launch_bounds__(512) void k_nms(const float* __restrict__ cls,
                                             const float* __restrict__ boxes, int N) {
    __shared__ u64 keys[CAPSH];
    __shared__ float sx1[TOPK], sy1[TOPK], sx2[TOPK], sy2[TOPK], sar[TOPK];
    __shared__ u64 smask[TOPK * 4];
    __shared__ u64 skeep[4];
    __shared__ u32 kw32[8];
    __shared__ int fh[256];
    __shared__ int s_flo, s_fc;

    int pc = blockIdx.x;
    int b = pc / CC, c = pc % CC;
    int tid = threadIdx.x;

    int cnt = d_candcnt[pc];
    bool good = (cnt <= CAPSH) && (cnt >= TOPK);

    int n;
    if (good) {
        n = 256;
        while (n < cnt) n <<= 1;
        for (int t = tid; t < n; t += 512)
            keys[t] = (t < cnt) ? d_cand[(size_t)pc * CAPSH + t] : 0ull;
    } else {
        // exact fallback: histogram + threshold + collect for this (b,c)
        n = CAPSH;
        if (tid < 256) fh[tid] = 0;
        if (tid == 0) s_fc = 0;
        __syncthreads();
        const float* col = cls + ((size_t)b * N) * CC + c;
        for (int i = tid; i < N; i += 512) {
            float v = col[(size_t)i * CC];
            if (v > 0.01f) {
                int bin = (int)(v * 256.0f); bin = bin > 255 ? 255 : bin;
                atomicAdd(&fh[bin], 1);
            }
        }
        __syncthreads();
        if (tid == 0) {
            int acc = 0, l2 = 0;
            for (int s = 255; s >= 0; s--) {
                acc += fh[s];
                if (acc >= TOPK) { l2 = s; break; }
            }
            s_flo = l2;
        }
        for (int t = tid; t < CAPSH; t += 512) keys[t] = 0ull;
        __syncthreads();
        float lof = (float)s_flo * 0.00390625f;
        for (int i = tid; i < N; i += 512) {
            float v = col[(size_t)i * CC];
            if (v > 0.01f && v >= lof) {
                int p = atomicAdd(&s_fc, 1);
                if (p < CAPSH)
                    keys[p] = ((u64)__float_as_uint(v) << 32) | (u64)(u32)(~(u32)i);
            }
        }
    }
    __syncthreads();
    bitonic_sort_desc(keys, n, tid, 512);

    if (tid < TOPK) {
        u64 k = keys[tid];
        if (k) {
            int id = (int)~(u32)(k & 0xFFFFFFFFull);
            float4 bx = reinterpret_cast<const float4*>(boxes)[(size_t)b * N + id];
            sx1[tid] = bx.x; sy1[tid] = bx.y; sx2[tid] = bx.z; sy2[tid] = bx.w;
            sar[tid] = fmaxf(bx.z - bx.x, 0.0f) * fmaxf(bx.w - bx.y, 0.0f);
        } else {
            sx1[tid] = 1e30f; sy1[tid] = 1e30f; sx2[tid] = -1e30f; sy2[tid] = -1e30f;
            sar[tid] = 0.0f;
        }
    }
    __syncthreads();

    if (tid < TOPK) {
        u64 m0 = 0, m1 = 0, m2 = 0, m3 = 0;
        float x1 = sx1[tid], y1 = sy1[tid], x2 = sx2[tid], y2 = sy2[tid], a = sar[tid];
        for (int j = tid + 1; j < TOPK; j++) {
            float xx1 = fmaxf(x1, sx1[j]), yy1 = fmaxf(y1, sy1[j]);
            float xx2 = fminf(x2, sx2[j]), yy2 = fminf(y2, sy2[j]);
            float inter = fmaxf(xx2 - xx1, 0.0f) * fmaxf(yy2 - yy1, 0.0f);
            float uni = a + sar[j] - inter;
            float iou = inter / fmaxf(uni, 1e-8f);
            if (iou > 0.5f) {
                if (j < 64)       m0 |= 1ull << j;
                else if (j < 128) m1 |= 1ull << (j - 64);
                else if (j < 192) m2 |= 1ull << (j - 128);
                else              m3 |= 1ull << (j - 192);
            }
        }
        smask[tid * 4 + 0] = m0; smask[tid * 4 + 1] = m1;
        smask[tid * 4 + 2] = m2; smask[tid * 4 + 3] = m3;
    }

    {
        unsigned pred = (tid < TOPK) && (keys[tid] != 0ull);
        unsigned bal = __ballot_sync(0xFFFFFFFFu, pred);
        int w = tid >> 5;
        if ((tid & 31) == 0 && w < 8) kw32[w] = bal;
    }
    __syncthreads();

    if (tid == 0) {
        u64 kw[4];
        #pragma unroll
        for (int w = 0; w < 4; w++)
            kw[w] = (u64)kw32[2 * w] | ((u64)kw32[2 * w + 1] << 32);
        for (int i = 0; i < TOPK; i++) {
            if ((kw[i >> 6] >> (i & 63)) & 1ull) {
                kw[0] &= ~smask[i * 4 + 0];
                kw[1] &= ~smask[i * 4 + 1];
                kw[2] &= ~smask[i * 4 + 2];
                kw[3] &= ~smask[i * 4 + 3];
            }
        }
        skeep[0] = kw[0]; skeep[1] = kw[1]; skeep[2] = kw[2]; skeep[3] = kw[3];
    }
    __syncthreads();

    if (tid < TOPK) {
        u64 k = keys[tid];
        d_nms_i[pc * TOPK + tid] = k ? (int)~(u32)(k & 0xFFFFFFFFull) : 0;
        bool kept = (k != 0ull) && (((skeep[tid >> 6] >> (tid & 63)) & 1ull) != 0ull);
        if (kept) {
            int w = tid >> 6, bit = tid & 63;
            int rank = 0;
            for (int x = 0; x < w; x++) rank += __popcll(skeep[x]);
            rank += __popcll(skeep[w] & ((bit == 0) ? 0ull : ((1ull << bit) - 1ull)));
            if (rank < MAXDET) {
                int pos = c * TOPK + tid;
                u64 key = ((k >> 32) << 13) | (u64)(8191 - pos);
                int p = atomicAdd(&d_poolcnt[b], 1);
                if (p < POOLCAP) d_pool[b * POOLCAP + p] = key;
            }
        }
    }
}

// Per-image merge: sort pool, write top-100 detections.
__global__ __launch_bounds__(1024) void k_merge(const float* __restrict__ boxes,
                                                const float* __restrict__ rot,
                                                const float* __restrict__ tr,
                                                float* __restrict__ out, int N) {
    __shared__ u64 skeys[4096];
    int b = blockIdx.x, tid = threadIdx.x;
    int cnt = min(d_poolcnt[b], POOLCAP);
    int n = 128;
    while (n < cnt) n <<= 1;
    for (int t = tid; t < n; t += 1024)
        skeys[t] = (t < cnt) ? d_pool[b * POOLCAP + t] : 0ull;
    __syncthreads();
    bitonic_sort_desc(skeys, n, tid, 1024);

    const int SC_OFF = BB * MAXDET * 4;
    const int LB_OFF = BB * MAXDET * 5;
    const int RT_OFF = BB * MAXDET * 6;
    const int TR_OFF = BB * MAXDET * 9;

    if (tid < MAXDET) {
        int o = b * MAXDET + tid;
        u64 k = skeys[tid];
        if (k) {
            float s = __uint_as_float((u32)(k >> 13));
            int pos = 8191 - (int)(k & 8191ull);
            int c = pos / TOPK;
            int idx = d_nms_i[b * CC * TOPK + pos];
            float4 bx = reinterpret_cast<const float4*>(boxes)[(size_t)b * N + idx];
            out[o * 4 + 0] = bx.x; out[o * 4 + 1] = bx.y;
            out[o * 4 + 2] = bx.z; out[o * 4 + 3] = bx.w;
            out[SC_OFF + o] = s;
            out[LB_OFF + o] = (float)c;
            size_t rb = ((size_t)b * N + idx) * 3;
            out[RT_OFF + o * 3 + 0] = rot[rb + 0];
            out[RT_OFF + o * 3 + 1] = rot[rb + 1];
            out[RT_OFF + o * 3 + 2] = rot[rb + 2];
            out[TR_OFF + o * 3 + 0] = tr[rb + 0];
            out[TR_OFF + o * 3 + 1] = tr[rb + 1];
            out[TR_OFF + o * 3 + 2] = tr[rb + 2];
        } else {
            out[o * 4 + 0] = -1.0f; out[o * 4 + 1] = -1.0f;
            out[o * 4 + 2] = -1.0f; out[o * 4 + 3] = -1.0f;
            out[SC_OFF + o] = -1.0f;
            out[LB_OFF + o] = -1.0f;
            out[RT_OFF + o * 3 + 0] = -1.0f;
            out[RT_OFF + o * 3 + 1] = -1.0f;
            out[RT_OFF + o * 3 + 2] = -1.0f;
            out[TR_OFF + o * 3 + 0] = -1.0f;
            out[TR_OFF + o * 3 + 1] = -1.0f;
            out[TR_OFF + o * 3 + 2] = -1.0f;
        }
    }
}

// ---------------- launch ----------------
extern "C" void kernel_launch(void* const* d_in, const int* in_sizes, int n_in,
                              void* d_out, int out_size) {
    const float* boxes = (const float*)d_in[0];
    const float* cls   = (const float*)d_in[1];
    const float* rot   = (const float*)d_in[2];
    const float* tr    = (const float*)d_in[3];
    float* out = (float*)d_out;
    int N = in_sizes[0] / (BB * 4);
    int tot4 = (in_sizes[1]) / 4;       // total classification elements / 4

    k_zero<<<1, 512>>>();
    k_collect<<<592, 512>>>(cls, tot4, N);
    k_nms<<<BB * CC, 512>>>(cls, boxes, N);
    k_merge<<<BB, 1024>>>(boxes, rot, tr, out, N);
}

// round 6
// speedup vs baseline: 1.5822x; 1.1182x over previous
#include <cuda_runtime.h>
#include <cstdint>

#define BB      16
#define CC      30
#define TOPK    200
#define MAXDET  100
#define CAPSH   2048          // per-(b,c) candidate capacity (shared sort size cap)
#define POOLCAP 3072
#define THRESH  0.995f

typedef unsigned long long u64;
typedef unsigned int u32;

// ---------------- scratch (device globals; no allocations) ----------------
// NOTE: zero-initialized at load; k_merge2 resets counters so every run starts clean.
__device__ int d_candcnt[BB * CC];
__device__ u64 d_cand[(size_t)BB * CC * CAPSH];
__device__ int d_nms_i[BB * CC * TOPK];
__device__ u64 d_pool[BB * POOLCAP];
__device__ int d_poolcnt[BB];
__device__ u64 d_top[BB * 4 * MAXDET];          // stage-A survivors

// ---------------- helpers ----------------
__device__ __forceinline__ void bitonic_sort_desc(u64* s, int n, int tid, int nt) {
    for (int k = 2; k <= n; k <<= 1) {
        for (int j = k >> 1; j > 0; j >>= 1) {
            for (int t = tid; t < n; t += nt) {
                int ixj = t ^ j;
                if (ixj > t) {
                    u64 a = s[t], b = s[ixj];
                    bool up = (t & k) == 0;
                    bool sw = up ? (a < b) : (a > b);
                    if (sw) { s[t] = b; s[ixj] = a; }
                }
            }
            __syncthreads();
        }
    }
}

// ---------------- kernels ----------------
// One full contiguous pass. Front-batched 8x float4 loads -> single gate compare.
__device__ __forceinline__ void coll_elem(float val, int ee, int N) {
    if (val >= THRESH) {
        u32 c = (u32)ee % CC;
        u32 r = (u32)ee / CC;           // flat row over all images
        u32 b = r / (u32)N;
        u32 i = r - b * (u32)N;
        int pcc = (int)(b * CC + c);
        int p = atomicAdd(&d_candcnt[pcc], 1);
        if (p < CAPSH)
            d_cand[(size_t)pcc * CAPSH + p] =
                ((u64)__float_as_uint(val) << 32) | (u64)(u32)(~i);
    }
}

__global__ __launch_bounds__(512) void k_collect(const float* __restrict__ cls,
                                                 int tot4, int N) {
    const float4* p4 = reinterpret_cast<const float4*>(cls);
    const float4 z4 = make_float4(0.f, 0.f, 0.f, 0.f);
    int ntiles = (tot4 + 4096 - 1) / 4096;           // tile = 512 threads * 8 quads
    for (int tile = blockIdx.x; tile < ntiles; tile += gridDim.x) {
        int v0 = tile * 4096 + threadIdx.x;
        float4 q[8];
        #pragma unroll
        for (int j = 0; j < 8; j++) {
            int idx = v0 + j * 512;
            q[j] = (idx < tot4) ? p4[idx] : z4;
        }
        float m = -1.f;
        #pragma unroll
        for (int j = 0; j < 8; j++)
            m = fmaxf(m, fmaxf(fmaxf(q[j].x, q[j].y), fmaxf(q[j].z, q[j].w)));
        if (m >= THRESH) {
            #pragma unroll
            for (int j = 0; j < 8; j++) {
                float mq = fmaxf(fmaxf(q[j].x, q[j].y), fmaxf(q[j].z, q[j].w));
                if (mq >= THRESH) {
                    int e = (v0 + j * 512) << 2;
                    coll_elem(q[j].x, e + 0, N);
                    coll_elem(q[j].y, e + 1, N);
                    coll_elem(q[j].z, e + 2, N);
                    coll_elem(q[j].w, e + 3, N);
                }
            }
        }
    }
}

// Per (b,c): exact top-200 + greedy NMS; emit compacted merge keys to pool.
__global__ __launch_bounds__(512) void k_nms(const float* __restrict__ cls,
                                             const float* __restrict__ boxes, int N) {
    __shared__ u64 keys[CAPSH];
    __shared__ float sx1[TOPK], sy1[TOPK], sx2[TOPK], sy2[TOPK], sar[TOPK];
    __shared__ u64 smask[TOPK * 4];
    __shared__ u64 skeep[4];
    __shared__ u32 kw32[8];
    __shared__ int fh[256];
    __shared__ int s_flo, s_fc;

    int pc = blockIdx.x;
    int b = pc / CC, c = pc % CC;
    int tid = threadIdx.x;

    int cnt = d_candcnt[pc];
    bool good = (cnt <= CAPSH) && (cnt >= TOPK);

    int n;
    if (good) {
        n = 256;
        while (n < cnt) n <<= 1;
        for (int t = tid; t < n; t += 512)
            keys[t] = (t < cnt) ? d_cand[(size_t)pc * CAPSH + t] : 0ull;
    } else {
        // exact fallback: histogram + threshold + collect for this (b,c)
        n = CAPSH;
        if (tid < 256) fh[tid] = 0;
        if (tid == 0) s_fc = 0;
        __syncthreads();
        const float* col = cls + ((size_t)b * N) * CC + c;
        for (int i = tid; i < N; i += 512) {
            float v = col[(size_t)i * CC];
            if (v > 0.01f) {
                int bin = (int)(v * 256.0f); bin = bin > 255 ? 255 : bin;
                atomicAdd(&fh[bin], 1);
            }
        }
        __syncthreads();
        if (tid == 0) {
            int acc = 0, l2 = 0;
            for (int s = 255; s >= 0; s--) {
                acc += fh[s];
                if (acc >= TOPK) { l2 = s; break; }
            }
            s_flo = l2;
        }
        for (int t = tid; t < CAPSH; t += 512) keys[t] = 0ull;
        __syncthreads();
        float lof = (float)s_flo * 0.00390625f;
        for (int i = tid; i < N; i += 512) {
            float v = col[(size_t)i * CC];
            if (v > 0.01f && v >= lof) {
                int p = atomicAdd(&s_fc, 1);
                if (p < CAPSH)
                    keys[p] = ((u64)__float_as_uint(v) << 32) | (u64)(u32)(~(u32)i);
            }
        }
    }
    __syncthreads();
    bitonic_sort_desc(keys, n, tid, 512);

    if (tid < TOPK) {
        u64 k = keys[tid];
        if (k) {
            int id = (int)~(u32)(k & 0xFFFFFFFFull);
            float4 bx = reinterpret_cast<const float4*>(boxes)[(size_t)b * N + id];
            sx1[tid] = bx.x; sy1[tid] = bx.y; sx2[tid] = bx.z; sy2[tid] = bx.w;
            sar[tid] = fmaxf(bx.z - bx.x, 0.0f) * fmaxf(bx.w - bx.y, 0.0f);
        } else {
            sx1[tid] = 1e30f; sy1[tid] = 1e30f; sx2[tid] = -1e30f; sy2[tid] = -1e30f;
            sar[tid] = 0.0f;
        }
    }
    __syncthreads();

    if (tid < TOPK) {
        u64 m0 = 0, m1 = 0, m2 = 0, m3 = 0;
        float x1 = sx1[tid], y1 = sy1[tid], x2 = sx2[tid], y2 = sy2[tid], a = sar[tid];
        for (int j = tid + 1; j < TOPK; j++) {
            float xx1 = fmaxf(x1, sx1[j]), yy1 = fmaxf(y1, sy1[j]);
            float xx2 = fminf(x2, sx2[j]), yy2 = fminf(y2, sy2[j]);
            float inter = fmaxf(xx2 - xx1, 0.0f) * fmaxf(yy2 - yy1, 0.0f);
            float uni = a + sar[j] - inter;
            float iou = inter / fmaxf(uni, 1e-8f);
            if (iou > 0.5f) {
                if (j < 64)       m0 |= 1ull << j;
                else if (j < 128) m1 |= 1ull << (j - 64);
                else if (j < 192) m2 |= 1ull << (j - 128);
                else              m3 |= 1ull << (j - 192);
            }
        }
        smask[tid * 4 + 0] = m0; smask[tid * 4 + 1] = m1;
        smask[tid * 4 + 2] = m2; smask[tid * 4 + 3] = m3;
    }

    {
        unsigned pred = (tid < TOPK) && (keys[tid] != 0ull);
        unsigned bal = __ballot_sync(0xFFFFFFFFu, pred);
        int w = tid >> 5;
        if ((tid & 31) == 0 && w < 8) kw32[w] = bal;
    }
    __syncthreads();

    if (tid == 0) {
        u64 kw[4];
        #pragma unroll
        for (int w = 0; w < 4; w++)
            kw[w] = (u64)kw32[2 * w] | ((u64)kw32[2 * w + 1] << 32);
        for (int i = 0; i < TOPK; i++) {
            if ((kw[i >> 6] >> (i & 63)) & 1ull) {
                kw[0] &= ~smask[i * 4 + 0];
                kw[1] &= ~smask[i * 4 + 1];
                kw[2] &= ~smask[i * 4 + 2];
                kw[3] &= ~smask[i * 4 + 3];
            }
        }
        skeep[0] = kw[0]; skeep[1] = kw[1]; skeep[2] = kw[2]; skeep[3] = kw[3];
    }
    __syncthreads();

    if (tid < TOPK) {
        u64 k = keys[tid];
        d_nms_i[pc * TOPK + tid] = k ? (int)~(u32)(k & 0xFFFFFFFFull) : 0;
        bool kept = (k != 0ull) && (((skeep[tid >> 6] >> (tid & 63)) & 1ull) != 0ull);
        if (kept) {
            int w = tid >> 6, bit = tid & 63;
            int rank = 0;
            for (int x = 0; x < w; x++) rank += __popcll(skeep[x]);
            rank += __popcll(skeep[w] & ((bit == 0) ? 0ull : ((1ull << bit) - 1ull)));
            if (rank < MAXDET) {
                int pos = c * TOPK + tid;
                u64 key = ((k >> 32) << 13) | (u64)(8191 - pos);
                int p = atomicAdd(&d_poolcnt[b], 1);
                if (p < POOLCAP) d_pool[b * POOLCAP + p] = key;
            }
        }
    }
}

// Merge stage A: 4 chunks x 16 images; sort each 768-entry chunk, keep top-100.
__global__ __launch_bounds__(512) void k_merge1() {
    __shared__ u64 buf[1024];
    int b = blockIdx.y, chunk = blockIdx.x, tid = threadIdx.x;
    int cnt = min(d_poolcnt[b], POOLCAP);
    int base = chunk * 768;
    for (int t = tid; t < 1024; t += 512) {
        int pos = base + t;
        buf[t] = (t < 768 && pos < cnt) ? d_pool[b * POOLCAP + pos] : 0ull;
    }
    __syncthreads();
    bitonic_sort_desc(buf, 1024, tid, 512);
    if (tid < MAXDET) d_top[(b * 4 + chunk) * MAXDET + tid] = buf[tid];
}

// Merge stage B: sort the 400 survivors, write top-100 detections, reset counters.
__global__ __launch_bounds__(512) void k_merge2(const float* __restrict__ boxes,
                                                const float* __restrict__ rot,
                                                const float* __restrict__ tr,
                                                float* __restrict__ out, int N) {
    __shared__ u64 skeys[512];
    int b = blockIdx.x, tid = threadIdx.x;
    skeys[tid] = (tid < 4 * MAXDET) ? d_top[b * 4 * MAXDET + tid] : 0ull;
    __syncthreads();
    bitonic_sort_desc(skeys, 512, tid, 512);

    const int SC_OFF = BB * MAXDET * 4;
    const int LB_OFF = BB * MAXDET * 5;
    const int RT_OFF = BB * MAXDET * 6;
    const int TR_OFF = BB * MAXDET * 9;

    if (tid < MAXDET) {
        int o = b * MAXDET + tid;
        u64 k = skeys[tid];
        if (k) {
            float s = __uint_as_float((u32)(k >> 13));
            int pos = 8191 - (int)(k & 8191ull);
            int c = pos / TOPK;
            int idx = d_nms_i[b * CC * TOPK + pos];
            float4 bx = reinterpret_cast<const float4*>(boxes)[(size_t)b * N + idx];
            out[o * 4 + 0] = bx.x; out[o * 4 + 1] = bx.y;
            out[o * 4 + 2] = bx.z; out[o * 4 + 3] = bx.w;
            out[SC_OFF + o] = s;
            out[LB_OFF + o] = (float)c;
            size_t rb = ((size_t)b * N + idx) * 3;
            out[RT_OFF + o * 3 + 0] = rot[rb + 0];
            out[RT_OFF + o * 3 + 1] = rot[rb + 1];
            out[RT_OFF + o * 3 + 2] = rot[rb + 2];
            out[TR_OFF + o * 3 + 0] = tr[rb + 0];
            out[TR_OFF + o * 3 + 1] = tr[rb + 1];
            out[TR_OFF + o * 3 + 2] = tr[rb + 2];
        } else {
            out[o * 4 + 0] = -1.0f; out[o * 4 + 1] = -1.0f;
            out[o * 4 + 2] = -1.0f; out[o * 4 + 3] = -1.0f;
            out[SC_OFF + o] = -1.0f;
            out[LB_OFF + o] = -1.0f;
            out[RT_OFF + o * 3 + 0] = -1.0f;
            out[RT_OFF + o * 3 + 1] = -1.0f;
            out[RT_OFF + o * 3 + 2] = -1.0f;
            out[TR_OFF + o * 3 + 0] = -1.0f;
            out[TR_OFF + o * 3 + 1] = -1.0f;
            out[TR_OFF + o * 3 + 2] = -1.0f;
        }
    }

    // reset counters for the next run (device globals start zeroed at load,
    // and every run leaves them zeroed -> deterministic across graph replays)
    if (tid < CC) d_candcnt[b * CC + tid] = 0;
    if (tid == CC) d_poolcnt[b] = 0;
}

// ---------------- launch ----------------
extern "C" void kernel_launch(void* const* d_in, const int* in_sizes, int n_in,
                              void* d_out, int out_size) {
    const float* boxes = (const float*)d_in[0];
    const float* cls   = (const float*)d_in[1];
    const float* rot   = (const float*)d_in[2];
    const float* tr    = (const float*)d_in[3];
    float* out = (float*)d_out;
    int N = in_sizes[0] / (BB * 4);
    int tot4 = (in_sizes[1]) / 4;       // total classification elements / 4

    k_collect<<<592, 512>>>(cls, tot4, N);
    k_nms<<<BB * CC, 512>>>(cls, boxes, N);
    k_merge1<<<dim3(4, BB), 512>>>();
    k_merge2<<<BB, 512>>>(boxes, rot, tr, out, N);
}